// round 15
// baseline (speedup 1.0000x reference)
#include <cuda_runtime.h>
#include <cstdint>

#define SEQ   2048
#define BATCH 128
#define INP   64
#define HID   256
#define GH    1024   // 4*HID
#define OUTD  64
#define NBG   16     // batch groups (8 batches each)
#define NUG   8      // unit groups  (32 units / 128 gate rows each)

typedef unsigned long long ull;

// packed 2xfp32 FMA (B300: FFMA-3reg is half rate; f32x2 restores full rate)
#define FMA2(d, a, b) asm("fma.rn.f32x2 %0, %1, %2, %0;" : "+l"(d) : "l"(a), "l"(b))

__device__ __forceinline__ float hsum2(ull v) {
    float2 f = *(float2*)&v;
    return f.x + f.y;
}

#define BAR_ARRIVE(id, cnt) \
    asm volatile("bar.arrive %0, %1;" :: "r"(id), "r"(cnt) : "memory")
#define BAR_SYNCN(id, cnt) \
    asm volatile("bar.sync %0, %1;"   :: "r"(id), "r"(cnt) : "memory")

// ---------------- scratch (static device arrays; no cudaMalloc) --------
__device__ float g_hs[(size_t)SEQ * BATCH * HID];  // h history (streamed)
__device__ float g_hx[2][BATCH * HID];             // hot h exchange (L2)
__device__ unsigned g_flag[NBG * NUG * 32];        // per-CTA publish flags (128B apart)
__device__ unsigned g_cnt;                          // one-shot global barriers
__device__ volatile unsigned g_gen;

// =============================================================
// Warp-specialized LSTM scan + readout (R14 skeleton).
// R15: compute thread tile R=4 rows x B=4 batches x K-quarter
// (lane = [ks2|bq1|rql2]): LDS instrs per thread 320 -> 128,
// H loads 1 full wavefront each. K-packed FMA2 (no dup ops).
// Strides retuned for bank behavior: WR/HS 276 (skew 68),
// Wx/X 84 (skew 20), Lsm 133.
// =============================================================
#define WR    276   // W_hh row stride: 4 k-slices of 68; 4*WR%32==16
#define KSK   68    // k-slice skew (W_hh/H)
#define HS    276   // H batch stride (same slicing as W rows)
#define HBUF  (8 * HS)        // 2208 floats per H parity buffer
#define LST2  133   // Lsm batch stride
#define WXR   84    // W_ih row stride: 4 k-slices of 20
#define KSX   20    // k-slice skew (W_ih/x)
#define XR    84    // x batch stride
#define XQ    (8 * XR)        // 672 floats per x buffer

#define SM_W   0
#define SM_WX  (128 * WR)            // 35328
#define SM_H   (SM_WX + 128 * WXR)   // 46080
#define SM_L   (SM_H + 2 * HBUF)     // 50496
#define SM_X   (SM_L + 8 * LST2)     // 51560
#define SM_TOT (SM_X + 4 * XQ + 32)  // 54280 floats = 217120 B

#define BARID_GATE 1
#define BARID_HRDY 2
#define BARID_CBAR 3

__device__ __forceinline__ void grid_barrier(int t) {
    if (t == 0) {
        unsigned cur = g_gen;
        __threadfence();
        if (atomicAdd(&g_cnt, 1u) == 127u) {
            atomicExch(&g_cnt, 0u);
            __threadfence();
            g_gen = cur + 1u;
        } else {
            while (g_gen == cur) { }
        }
        __threadfence();
    }
    __syncthreads();
}

__global__ void __launch_bounds__(512, 1)
k_lstm(const float* __restrict__ x, const float* __restrict__ h0,
       const float* __restrict__ c0, const float* __restrict__ Whh,
       const float* __restrict__ Wih, const float* __restrict__ bias,
       const float* __restrict__ Wout, const float* __restrict__ bout,
       float* __restrict__ out)
{
    extern __shared__ float smR[];
    float* Wsm  = smR + SM_W;    // W_hh [row r][ks*68 + kk]
    float* Wxsm = smR + SM_WX;   // W_ih [row r][ks*20 + kk]
    float* Hsm  = smR + SM_H;    // h [par][b][ks*68 + kk]
    float* Lsm  = smR + SM_L;    // lin [b][row 0..127]
    float* Xsm  = smR + SM_X;    // x [q][b][ks*20 + kk]

    const int t     = threadIdx.x;
    const int bgrp  = blockIdx.x >> 3;      // 0..15
    const int urank = blockIdx.x & 7;       // 0..7
    const int b0g   = bgrp << 3;            // global batch base
    const int u0    = urank << 5;           // global unit base

    // ---- reset my publish flag ----
    unsigned* myflag = &g_flag[(bgrp * NUG + urank) * 32];
    if (t == 0) *myflag = 0u;

    // ---- load W_hh slice (sliced k layout) ----
    for (int idx = t; idx < 128 * 64; idx += 512) {
        int r = idx >> 6, c4 = idx & 63;
        int grow = ((r >> 5) << 8) + u0 + (r & 31);
        float4 v = ((const float4*)Whh)[(size_t)grow * 64 + c4];
        *(float4*)(Wsm + r * WR + (c4 >> 4) * KSK + ((c4 & 15) << 2)) = v;
    }
    // ---- load W_ih slice ----
    for (int idx = t; idx < 128 * 16; idx += 512) {
        int r = idx >> 4, c4 = idx & 15;
        int grow = ((r >> 5) << 8) + u0 + (r & 31);
        float4 v = ((const float4*)Wih)[(size_t)grow * 16 + c4];
        *(float4*)(Wxsm + r * WXR + (c4 >> 2) * KSX + ((c4 & 3) << 2)) = v;
    }
    // ---- init Hsm[0] from h0 ----
    {
        int b = t >> 6, c4 = t & 63;
        float4 v = ((const float4*)h0)[(size_t)(b0g + b) * 64 + c4];
        *(float4*)(Hsm + b * HS + (c4 >> 4) * KSK + ((c4 & 15) << 2)) = v;
    }
    // ---- init Xsm[0]=x(0), Xsm[1]=x(1); xr = x(2) (t<128) ----
    float4 xr = make_float4(0.f, 0.f, 0.f, 0.f);
    if (t < 128) {
        int b = t >> 4, c4 = t & 15;
        int xo = b * XR + (c4 >> 2) * KSX + ((c4 & 3) << 2);
        *(float4*)(Xsm + 0 * XQ + xo) =
            ((const float4*)x)[(size_t)(b0g + b) * 16 + c4];
        *(float4*)(Xsm + 1 * XQ + xo) =
            ((const float4*)x)[(size_t)(BATCH + b0g + b) * 16 + c4];
        xr = ((const float4*)x)[(size_t)(2 * BATCH + b0g + b) * 16 + c4];
    }

    // ---- comm-thread state (t < 256) ----
    const int b_c = t >> 5;
    const int u_c = t & 31;
    const int ugt = u0 + u_c;
    float creg = 0.f, bi = 0.f, bf = 0.f, bg = 0.f, bo = 0.f;
    if (t < 256) {
        creg = c0[(size_t)(b0g + b_c) * HID + ugt];
        bi = bias[0 * HID + ugt];
        bf = bias[1 * HID + ugt];
        bg = bias[2 * HID + ugt];
        bo = bias[3 * HID + ugt];
    }
    // staging: 2 float4s per comm thread (global units j0*4.., j1*4..)
    const int j0 = u_c, j1 = u_c + 32;
    const unsigned* f0 = &g_flag[(bgrp * NUG + (j0 >> 3)) * 32];
    const unsigned* f1 = &g_flag[(bgrp * NUG + (j1 >> 3)) * 32];
    const int hxoff0 = (b0g + b_c) * HID + (j0 << 2);
    const int hxoff1 = (b0g + b_c) * HID + (j1 << 2);
    const int hso0 = b_c * HS + (j0 >> 4) * KSK + ((j0 & 15) << 2);
    const int hso1 = b_c * HS + (j1 >> 4) * KSK + ((j1 & 15) << 2);

    grid_barrier(t);   // flags zeroed everywhere before first publish

    if (t < 256) {
        // ======================= COMM + GATES =======================
        #pragma unroll 1
        for (int step = 0; step < SEQ; step++) {
            const int par = step & 1;
            BAR_SYNCN(BARID_GATE, 512);          // Lsm(step) ready

            const float* Lb = Lsm + b_c * LST2;
            float iv = Lb[u_c]      + bi;
            float fv = Lb[32 + u_c] + bf;
            float gv = Lb[64 + u_c] + bg;
            float ov = Lb[96 + u_c] + bo;
            float ig = 1.f / (1.f + __expf(-iv));
            float fg = 1.f / (1.f + __expf(-fv));
            float gg = tanhf(gv);
            float og = 1.f / (1.f + __expf(-ov));
            float cc = fg * creg + ig * gg;
            creg = cc;
            float hh = og * tanhf(cc);
            g_hx[par][(b0g + b_c) * HID + ugt] = hh;

            // x stage 2 ahead (t<128)
            if (t < 128 && step + 2 < SEQ) {
                int b = t >> 4, c4 = t & 15;
                *(float4*)(Xsm + ((step + 2) & 3) * XQ + b * XR +
                           (c4 >> 2) * KSX + ((c4 & 3) << 2)) = xr;
                if (step + 3 < SEQ)
                    xr = ((const float4*)x)[(size_t)((step + 3) * BATCH + b0g + b) * 16 + c4];
            }

            BAR_SYNCN(BARID_CBAR, 256);          // all publishes issued
            if (t == 0) {
                unsigned nv = (unsigned)(step + 1);
                asm volatile("st.release.gpu.u32 [%0], %1;"
                             :: "l"(myflag), "r"(nv) : "memory");
            }
            __stcs(&g_hs[((size_t)step * BATCH + b0g + b_c) * HID + ugt], hh);

            if (step + 1 < SEQ) {
                unsigned v;
                do {
                    asm volatile("ld.acquire.gpu.u32 %0, [%1];"
                                 : "=r"(v) : "l"(f0) : "memory");
                } while (v < (unsigned)(step + 1));
                float4 hva = *(const float4*)&g_hx[par][hxoff0];
                do {
                    asm volatile("ld.acquire.gpu.u32 %0, [%1];"
                                 : "=r"(v) : "l"(f1) : "memory");
                } while (v < (unsigned)(step + 1));
                float4 hvb = *(const float4*)&g_hx[par][hxoff1];
                float* Hd = Hsm + ((step + 1) & 1) * HBUF;
                *(float4*)(Hd + hso0) = hva;
                *(float4*)(Hd + hso1) = hvb;
                BAR_ARRIVE(BARID_HRDY, 512);     // h(step) staged for step+1
            }
        }
    } else {
        // ========================= COMPUTE ==========================
        // lane = [ks(2) | bq(1) | rql(2)], rq = w8*4 + rql
        const int ct   = t - 256;
        const int lane = ct & 31;
        const int w8   = ct >> 5;           // 0..7
        const int rql  = lane & 3;
        const int bq   = (lane >> 2) & 1;
        const int ks   = lane >> 3;         // 0..3
        const int rq   = (w8 << 2) + rql;   // 0..31
        const int r0   = rq << 2;           // base row (4 rows r0..r0+3)
        const int bb   = bq << 2;           // base batch (4 batches)

        const float* W0  = Wsm  + (r0 + 0) * WR + ks * KSK;
        const float* W1  = Wsm  + (r0 + 1) * WR + ks * KSK;
        const float* W2  = Wsm  + (r0 + 2) * WR + ks * KSK;
        const float* W3  = Wsm  + (r0 + 3) * WR + ks * KSK;
        const float* Wx0 = Wxsm + (r0 + 0) * WXR + ks * KSX;
        const float* Wx1 = Wxsm + (r0 + 1) * WXR + ks * KSX;
        const float* Wx2 = Wxsm + (r0 + 2) * WXR + ks * KSX;
        const float* Wx3 = Wxsm + (r0 + 3) * WXR + ks * KSX;

        #pragma unroll 1
        for (int step = 0; step < SEQ; step++) {
            ull acc[4][4];
            #pragma unroll
            for (int i = 0; i < 4; i++)
                #pragma unroll
                for (int j = 0; j < 4; j++) acc[i][j] = 0ull;

            // ---- x-GEMV first (overlaps comm's publish->poll->stage) ----
            {
                const float* Xb = Xsm + (step & 3) * XQ + bb * XR + ks * KSX;
                #pragma unroll
                for (int kx = 0; kx < 4; kx++) {
                    ulonglong2 w0 = *(const ulonglong2*)(Wx0 + (kx << 2));
                    ulonglong2 w1 = *(const ulonglong2*)(Wx1 + (kx << 2));
                    ulonglong2 w2 = *(const ulonglong2*)(Wx2 + (kx << 2));
                    ulonglong2 w3 = *(const ulonglong2*)(Wx3 + (kx << 2));
                    #pragma unroll
                    for (int j = 0; j < 4; j++) {
                        ulonglong2 hv = *(const ulonglong2*)(Xb + j * XR + (kx << 2));
                        FMA2(acc[0][j], w0.x, hv.x); FMA2(acc[0][j], w0.y, hv.y);
                        FMA2(acc[1][j], w1.x, hv.x); FMA2(acc[1][j], w1.y, hv.y);
                        FMA2(acc[2][j], w2.x, hv.x); FMA2(acc[2][j], w2.y, hv.y);
                        FMA2(acc[3][j], w3.x, hv.x); FMA2(acc[3][j], w3.y, hv.y);
                    }
                }
            }
            if (step > 0) BAR_SYNCN(BARID_HRDY, 512);   // h(step-1) staged

            // ---- h-GEMV: 4 rows x 4 batches x K-quarter ----
            {
                const float* Hb = Hsm + (step & 1) * HBUF + bb * HS + ks * KSK;
                #pragma unroll 2
                for (int kk = 0; kk < 16; kk++) {
                    ulonglong2 w0 = *(const ulonglong2*)(W0 + (kk << 2));
                    ulonglong2 w1 = *(const ulonglong2*)(W1 + (kk << 2));
                    ulonglong2 w2 = *(const ulonglong2*)(W2 + (kk << 2));
                    ulonglong2 w3 = *(const ulonglong2*)(W3 + (kk << 2));
                    #pragma unroll
                    for (int j = 0; j < 4; j++) {
                        ulonglong2 hv = *(const ulonglong2*)(Hb + j * HS + (kk << 2));
                        FMA2(acc[0][j], w0.x, hv.x); FMA2(acc[0][j], w0.y, hv.y);
                        FMA2(acc[1][j], w1.x, hv.x); FMA2(acc[1][j], w1.y, hv.y);
                        FMA2(acc[2][j], w2.x, hv.x); FMA2(acc[2][j], w2.y, hv.y);
                        FMA2(acc[3][j], w3.x, hv.x); FMA2(acc[3][j], w3.y, hv.y);
                    }
                }
            }

            // ---- reduce over ks lanes (bits 3,4) and write Lsm ----
            #pragma unroll
            for (int i = 0; i < 4; i++) {
                #pragma unroll
                for (int j = 0; j < 4; j++) {
                    float s = hsum2(acc[i][j]);
                    s += __shfl_xor_sync(~0u, s, 8);
                    s += __shfl_xor_sync(~0u, s, 16);
                    if (ks == 0)
                        Lsm[(bb + j) * LST2 + r0 + i] = s;
                }
            }
            BAR_ARRIVE(BARID_GATE, 512);
        }
    }

    // ================= readout: out = hs @ Wout^T + bout =================
    __threadfence();
    grid_barrier(t);

    ulonglong2* WoS = (ulonglong2*)smR;            // [kc][64][19]
    ulonglong2* HsS = (ulonglong2*)(smR + SM_H);   // [64][19]

    for (int idx = t; idx < 4096; idx += 512) {
        int kc = idx >> 10, rem = idx & 1023, rr = rem >> 4, c = rem & 15;
        WoS[(kc * 64 + rr) * 19 + c] =
            ((const ulonglong2*)Wout)[(size_t)rr * 64 + kc * 16 + c];
    }
    const int tx  = t & 15;
    const int tyr = t >> 4;   // 0..31
    float bo4[4];
    #pragma unroll
    for (int j = 0; j < 4; j++) bo4[j] = __ldg(&bout[tx + 16 * j]);
    __syncthreads();

    for (int tile = 0; tile < 32; tile++) {
        size_t m0 = ((size_t)blockIdx.x * 32 + tile) * 64;
        ull ac[2][4];
        #pragma unroll
        for (int i = 0; i < 2; i++)
            #pragma unroll
            for (int j = 0; j < 4; j++) ac[i][j] = 0ull;

        for (int kc = 0; kc < 4; kc++) {
            __syncthreads();
            for (int idx = t; idx < 1024; idx += 512) {
                int rr = idx >> 4, c = idx & 15;
                HsS[rr * 19 + c] =
                    ((const ulonglong2*)g_hs)[(m0 + rr) * 64 + kc * 16 + c];
            }
            __syncthreads();
            #pragma unroll
            for (int k4 = 0; k4 < 16; k4++) {
                ulonglong2 a0 = HsS[tyr * 19 + k4];
                ulonglong2 a1 = HsS[(tyr + 32) * 19 + k4];
                #pragma unroll
                for (int j = 0; j < 4; j++) {
                    ulonglong2 b2 = WoS[(kc * 64 + tx + 16 * j) * 19 + k4];
                    FMA2(ac[0][j], a0.x, b2.x); FMA2(ac[0][j], a0.y, b2.y);
                    FMA2(ac[1][j], a1.x, b2.x); FMA2(ac[1][j], a1.y, b2.y);
                }
            }
        }
        #pragma unroll
        for (int i = 0; i < 2; i++) {
            size_t m = m0 + tyr + 32 * i;
            #pragma unroll
            for (int j = 0; j < 4; j++)
                out[m * OUTD + tx + 16 * j] = hsum2(ac[i][j]) + bo4[j];
        }
    }
}

// =============================================================
extern "C" void kernel_launch(void* const* d_in, const int* in_sizes, int n_in,
                              void* d_out, int out_size)
{
    (void)in_sizes; (void)n_in; (void)out_size;
    const float* x    = (const float*)d_in[0];
    const float* h0   = (const float*)d_in[1];
    const float* c0   = (const float*)d_in[2];
    const float* Wih  = (const float*)d_in[3];
    const float* Whh  = (const float*)d_in[4];
    const float* b    = (const float*)d_in[5];
    const float* Wout = (const float*)d_in[6];
    const float* bout = (const float*)d_in[7];
    float* out = (float*)d_out;

    const int smB = SM_TOT * 4;   // 217120 B

    cudaFuncSetAttribute(k_lstm, cudaFuncAttributeMaxDynamicSharedMemorySize, smB);

    k_lstm<<<NBG * NUG, 512, smB>>>(x, h0, c0, Whh, Wih, b, Wout, bout, out);
}

// round 16
// speedup vs baseline: 1.0486x; 1.0486x over previous
#include <cuda_runtime.h>
#include <cstdint>

#define SEQ   2048
#define BATCH 128
#define INP   64
#define HID   256
#define GH    1024   // 4*HID
#define OUTD  64
#define NBG   16     // batch groups (8 batches each)
#define NUG   8      // unit groups  (32 units / 128 gate rows each)

typedef unsigned long long ull;

// packed 2xfp32 FMA (B300: FFMA-3reg is half rate; f32x2 restores full rate)
#define FMA2(d, a, b) asm("fma.rn.f32x2 %0, %1, %2, %0;" : "+l"(d) : "l"(a), "l"(b))

__device__ __forceinline__ float hsum2(ull v) {
    float2 f = *(float2*)&v;
    return f.x + f.y;
}

#define BAR_ARRIVE(id, cnt) \
    asm volatile("bar.arrive %0, %1;" :: "r"(id), "r"(cnt) : "memory")
#define BAR_SYNCN(id, cnt) \
    asm volatile("bar.sync %0, %1;"   :: "r"(id), "r"(cnt) : "memory")

// ---------------- scratch (static device arrays; no cudaMalloc) --------
__device__ float g_hs[(size_t)SEQ * BATCH * HID];  // h history (streamed)
__device__ float g_hx[2][BATCH * HID];             // hot h exchange (L2)
__device__ unsigned g_flag[NBG * NUG * 32];        // per-CTA publish flags (128B apart)
__device__ unsigned g_cnt;                          // one-shot global barriers
__device__ volatile unsigned g_gen;

// =============================================================
// Warp-specialized LSTM scan + readout (R14 skeleton, best=10.44ms).
// R16: single-flag staging — each comm thread's two float4s come
// from ONE source rank (8 consecutive floats), so the exchange
// chain is poll(1 flag) -> 2 parallel data loads: 2 L2 RTTs
// instead of R14's 3-4 dependent RTTs.
// =============================================================
#define WR    260   // W_hh row stride (floats)
#define WXR   68    // W_ih row stride
#define HS2   260   // H batch stride
#define HBUF2 (8 * HS2)      // 2080 floats per H parity buffer
#define LST2  132   // L batch stride
#define XB    68    // x batch stride
#define XQ    (8 * XB)       // 544 floats per x buffer (x4 quad)

#define SM_W   0
#define SM_WX  (128 * WR)            // 33280
#define SM_H   (SM_WX + 128 * WXR)   // 41984
#define SM_L   (SM_H + 2 * HBUF2)    // 46144
#define SM_X   (SM_L + 8 * LST2)     // 47200
#define SM_TOT (SM_X + 4 * XQ + 32)  // 49408 floats = 197632 B

#define BARID_GATE 1
#define BARID_HRDY 2
#define BARID_CBAR 3

__device__ __forceinline__ void grid_barrier(int t) {
    if (t == 0) {
        unsigned cur = g_gen;
        __threadfence();
        if (atomicAdd(&g_cnt, 1u) == 127u) {
            atomicExch(&g_cnt, 0u);
            __threadfence();
            g_gen = cur + 1u;
        } else {
            while (g_gen == cur) { }
        }
        __threadfence();
    }
    __syncthreads();
}

__global__ void __launch_bounds__(512, 1)
k_lstm(const float* __restrict__ x, const float* __restrict__ h0,
       const float* __restrict__ c0, const float* __restrict__ Whh,
       const float* __restrict__ Wih, const float* __restrict__ bias,
       const float* __restrict__ Wout, const float* __restrict__ bout,
       float* __restrict__ out)
{
    extern __shared__ float smR[];
    float* Wsm  = smR + SM_W;    // W_hh [row r][k 0..255], stride WR
    float* Wxsm = smR + SM_WX;   // W_ih [row r][k 0..63], stride WXR
    float* Hsm  = smR + SM_H;    // h [par][b][k 0..255]
    float* Lsm  = smR + SM_L;    // lin [b][row 0..127]
    float* Xsm  = smR + SM_X;    // x [q 0..3][b][k 0..63]

    const int t     = threadIdx.x;
    const int bgrp  = blockIdx.x >> 3;      // 0..15
    const int urank = blockIdx.x & 7;       // 0..7
    const int b0g   = bgrp << 3;            // global batch base
    const int u0    = urank << 5;           // global unit base

    // ---- reset my publish flag ----
    unsigned* myflag = &g_flag[(bgrp * NUG + urank) * 32];
    if (t == 0) *myflag = 0u;

    // ---- load W_hh slice (128 rows x 256 K, linear k) ----
    for (int idx = t; idx < 128 * 64; idx += 512) {
        int r = idx >> 6, c4 = idx & 63;
        int grow = ((r >> 5) << 8) + u0 + (r & 31);
        float4 v = ((const float4*)Whh)[(size_t)grow * 64 + c4];
        *(float4*)(Wsm + r * WR + (c4 << 2)) = v;
    }
    // ---- load W_ih slice (128 rows x 64 K) ----
    for (int idx = t; idx < 128 * 16; idx += 512) {
        int r = idx >> 4, c4 = idx & 15;
        int grow = ((r >> 5) << 8) + u0 + (r & 31);
        float4 v = ((const float4*)Wih)[(size_t)grow * 16 + c4];
        *(float4*)(Wxsm + r * WXR + (c4 << 2)) = v;
    }
    // ---- init Hsm[0] from h0 ----
    {
        int b = t >> 6, c4 = t & 63;
        float4 v = ((const float4*)h0)[(size_t)(b0g + b) * 64 + c4];
        *(float4*)(Hsm + b * HS2 + (c4 << 2)) = v;
    }
    // ---- init Xsm[0]=x(0), Xsm[1]=x(1); xr = x(2) (t<128) ----
    float4 xr = make_float4(0.f, 0.f, 0.f, 0.f);
    if (t < 128) {
        int b = t >> 4, c4 = t & 15;
        *(float4*)(Xsm + 0 * XQ + b * XB + (c4 << 2)) =
            ((const float4*)x)[(size_t)(b0g + b) * 16 + c4];
        *(float4*)(Xsm + 1 * XQ + b * XB + (c4 << 2)) =
            ((const float4*)x)[(size_t)(BATCH + b0g + b) * 16 + c4];
        xr = ((const float4*)x)[(size_t)(2 * BATCH + b0g + b) * 16 + c4];
    }

    // ---- comm-thread state (t < 256) ----
    const int b_c = t >> 5;
    const int u_c = t & 31;
    const int ugt = u0 + u_c;
    float creg = 0.f, bi = 0.f, bf = 0.f, bg = 0.f, bo = 0.f;
    if (t < 256) {
        creg = c0[(size_t)(b0g + b_c) * HID + ugt];
        bi = bias[0 * HID + ugt];
        bf = bias[1 * HID + ugt];
        bg = bias[2 * HID + ugt];
        bo = bias[3 * HID + ugt];
    }
    // ---- R16 staging: ONE source rank per thread, 8 consecutive floats ----
    const int rnk = u_c & 7;            // source rank
    const int sid = u_c >> 3;           // 0..3
    const int j0  = rnk * 8 + sid * 2;  // first float4 index (j0, j0+1)
    const unsigned* fsrc = &g_flag[(bgrp * NUG + rnk) * 32];
    const int hxo = (b0g + b_c) * HID + (j0 << 2);
    const int hdo = b_c * HS2 + (j0 << 2);

    grid_barrier(t);   // flags zeroed everywhere before first publish

    if (t < 256) {
        // ======================= COMM + GATES =======================
        #pragma unroll 1
        for (int step = 0; step < SEQ; step++) {
            const int par = step & 1;
            BAR_SYNCN(BARID_GATE, 512);          // Lsm(step) ready

            const float* Lb = Lsm + b_c * LST2;
            float iv = Lb[u_c]      + bi;
            float fv = Lb[32 + u_c] + bf;
            float gv = Lb[64 + u_c] + bg;
            float ov = Lb[96 + u_c] + bo;
            float ig = 1.f / (1.f + __expf(-iv));
            float fg = 1.f / (1.f + __expf(-fv));
            float gg = tanhf(gv);
            float og = 1.f / (1.f + __expf(-ov));
            float cc = fg * creg + ig * gg;
            creg = cc;
            float hh = og * tanhf(cc);
            g_hx[par][(b0g + b_c) * HID + ugt] = hh;

            // x stage 2 ahead (t<128)
            if (t < 128 && step + 2 < SEQ) {
                int b = t >> 4, c4 = t & 15;
                *(float4*)(Xsm + ((step + 2) & 3) * XQ + b * XB + (c4 << 2)) = xr;
                if (step + 3 < SEQ)
                    xr = ((const float4*)x)[(size_t)((step + 3) * BATCH + b0g + b) * 16 + c4];
            }

            BAR_SYNCN(BARID_CBAR, 256);          // all publishes issued
            if (t == 0) {
                unsigned nv = (unsigned)(step + 1);
                asm volatile("st.release.gpu.u32 [%0], %1;"
                             :: "l"(myflag), "r"(nv) : "memory");
            }
            __stcs(&g_hs[((size_t)step * BATCH + b0g + b_c) * HID + ugt], hh);

            if (step + 1 < SEQ) {
                // poll ONE flag, then two parallel data loads
                unsigned v;
                do {
                    asm volatile("ld.acquire.gpu.u32 %0, [%1];"
                                 : "=r"(v) : "l"(fsrc) : "memory");
                } while (v < (unsigned)(step + 1));
                float4 hva = *(const float4*)&g_hx[par][hxo];
                float4 hvb = *(const float4*)&g_hx[par][hxo + 4];
                float* Hd = Hsm + ((step + 1) & 1) * HBUF2 + hdo;
                *(float4*)(Hd)     = hva;
                *(float4*)(Hd + 4) = hvb;
                BAR_ARRIVE(BARID_HRDY, 512);     // h(step) staged for step+1
            }
        }
    } else {
        // ========================= COMPUTE ==========================
        const int ct = t - 256;
        const int r  = ct >> 1;        // gate row 0..127
        const int bp = ct & 1;         // batch half
        const int bb = bp << 2;        // batch base 0 or 4
        const float* Wrow  = Wsm  + r * WR;
        const float* Wxrow = Wxsm + r * WXR;

        #pragma unroll 1
        for (int step = 0; step < SEQ; step++) {
            // ---- x-GEMV first (overlaps comm's publish->poll->stage) ----
            ull a0 = 0, a1 = 0, a2 = 0, a3 = 0;
            {
                const float* Xq = Xsm + (step & 3) * XQ + bb * XB;
                #pragma unroll
                for (int k2 = 0; k2 < 16; k2++) {
                    ulonglong2 wv = *(const ulonglong2*)(Wxrow + (k2 << 2));
                    ulonglong2 hv;
                    hv = *(const ulonglong2*)(Xq + 0 * XB + (k2 << 2));
                    FMA2(a0, wv.x, hv.x); FMA2(a0, wv.y, hv.y);
                    hv = *(const ulonglong2*)(Xq + 1 * XB + (k2 << 2));
                    FMA2(a1, wv.x, hv.x); FMA2(a1, wv.y, hv.y);
                    hv = *(const ulonglong2*)(Xq + 2 * XB + (k2 << 2));
                    FMA2(a2, wv.x, hv.x); FMA2(a2, wv.y, hv.y);
                    hv = *(const ulonglong2*)(Xq + 3 * XB + (k2 << 2));
                    FMA2(a3, wv.x, hv.x); FMA2(a3, wv.y, hv.y);
                }
            }
            if (step > 0) BAR_SYNCN(BARID_HRDY, 512);   // h(step-1) staged

            // ---- h-GEMV: full K=256, 1 row x 4 batches ----
            {
                const float* Hb = Hsm + (step & 1) * HBUF2 + bb * HS2;
                #pragma unroll 8
                for (int k2 = 0; k2 < 64; k2++) {
                    ulonglong2 wv = *(const ulonglong2*)(Wrow + (k2 << 2));
                    ulonglong2 hv;
                    hv = *(const ulonglong2*)(Hb + 0 * HS2 + (k2 << 2));
                    FMA2(a0, wv.x, hv.x); FMA2(a0, wv.y, hv.y);
                    hv = *(const ulonglong2*)(Hb + 1 * HS2 + (k2 << 2));
                    FMA2(a1, wv.x, hv.x); FMA2(a1, wv.y, hv.y);
                    hv = *(const ulonglong2*)(Hb + 2 * HS2 + (k2 << 2));
                    FMA2(a2, wv.x, hv.x); FMA2(a2, wv.y, hv.y);
                    hv = *(const ulonglong2*)(Hb + 3 * HS2 + (k2 << 2));
                    FMA2(a3, wv.x, hv.x); FMA2(a3, wv.y, hv.y);
                }
            }
            // ---- Lsm: 4 scalar stores (no shfl reduce needed) ----
            Lsm[(bb + 0) * LST2 + r] = hsum2(a0);
            Lsm[(bb + 1) * LST2 + r] = hsum2(a1);
            Lsm[(bb + 2) * LST2 + r] = hsum2(a2);
            Lsm[(bb + 3) * LST2 + r] = hsum2(a3);
            BAR_ARRIVE(BARID_GATE, 512);
        }
    }

    // ================= readout: out = hs @ Wout^T + bout =================
    __threadfence();
    grid_barrier(t);

    ulonglong2* WoS = (ulonglong2*)smR;            // [kc][64][19]
    ulonglong2* HsS = (ulonglong2*)(smR + SM_H);   // [64][19]

    for (int idx = t; idx < 4096; idx += 512) {
        int kc = idx >> 10, rem = idx & 1023, rr = rem >> 4, c = rem & 15;
        WoS[(kc * 64 + rr) * 19 + c] =
            ((const ulonglong2*)Wout)[(size_t)rr * 64 + kc * 16 + c];
    }
    const int tx  = t & 15;
    const int tyr = t >> 4;   // 0..31
    float bo4[4];
    #pragma unroll
    for (int j = 0; j < 4; j++) bo4[j] = __ldg(&bout[tx + 16 * j]);
    __syncthreads();

    for (int tile = 0; tile < 32; tile++) {
        size_t m0 = ((size_t)blockIdx.x * 32 + tile) * 64;
        ull ac[2][4];
        #pragma unroll
        for (int i = 0; i < 2; i++)
            #pragma unroll
            for (int j = 0; j < 4; j++) ac[i][j] = 0ull;

        for (int kc = 0; kc < 4; kc++) {
            __syncthreads();
            for (int idx = t; idx < 1024; idx += 512) {
                int rr = idx >> 4, c = idx & 15;
                HsS[rr * 19 + c] =
                    ((const ulonglong2*)g_hs)[(m0 + rr) * 64 + kc * 16 + c];
            }
            __syncthreads();
            #pragma unroll
            for (int k4 = 0; k4 < 16; k4++) {
                ulonglong2 a0 = HsS[tyr * 19 + k4];
                ulonglong2 a1 = HsS[(tyr + 32) * 19 + k4];
                #pragma unroll
                for (int j = 0; j < 4; j++) {
                    ulonglong2 b2 = WoS[(kc * 64 + tx + 16 * j) * 19 + k4];
                    FMA2(ac[0][j], a0.x, b2.x); FMA2(ac[0][j], a0.y, b2.y);
                    FMA2(ac[1][j], a1.x, b2.x); FMA2(ac[1][j], a1.y, b2.y);
                }
            }
        }
        #pragma unroll
        for (int i = 0; i < 2; i++) {
            size_t m = m0 + tyr + 32 * i;
            #pragma unroll
            for (int j = 0; j < 4; j++)
                out[m * OUTD + tx + 16 * j] = hsum2(ac[i][j]) + bo4[j];
        }
    }
}

// =============================================================
extern "C" void kernel_launch(void* const* d_in, const int* in_sizes, int n_in,
                              void* d_out, int out_size)
{
    (void)in_sizes; (void)n_in; (void)out_size;
    const float* x    = (const float*)d_in[0];
    const float* h0   = (const float*)d_in[1];
    const float* c0   = (const float*)d_in[2];
    const float* Wih  = (const float*)d_in[3];
    const float* Whh  = (const float*)d_in[4];
    const float* b    = (const float*)d_in[5];
    const float* Wout = (const float*)d_in[6];
    const float* bout = (const float*)d_in[7];
    float* out = (float*)d_out;

    const int smB = SM_TOT * 4;   // 197632 B

    cudaFuncSetAttribute(k_lstm, cudaFuncAttributeMaxDynamicSharedMemorySize, smB);

    k_lstm<<<NBG * NUG, 512, smB>>>(x, h0, c0, Whh, Wih, b, Wout, bout, out);
}

// round 17
// speedup vs baseline: 1.2540x; 1.1959x over previous
#include <cuda_runtime.h>
#include <cstdint>

#define SEQ   2048
#define BATCH 128
#define INP   64
#define HID   256
#define GH    1024   // 4*HID
#define OUTD  64
#define NBG   16     // batch groups (8 batches each)
#define NUG   8      // unit groups  (32 units / 128 gate rows each)

typedef unsigned long long ull;

// packed 2xfp32 FMA (B300: FFMA-3reg is half rate; f32x2 restores full rate)
#define FMA2(d, a, b) asm("fma.rn.f32x2 %0, %1, %2, %0;" : "+l"(d) : "l"(a), "l"(b))

__device__ __forceinline__ float hsum2(ull v) {
    float2 f = *(float2*)&v;
    return f.x + f.y;
}

// fast transcendentals: MUFU-only sigmoid/tanh (per-op err ~1e-6, safe)
__device__ __forceinline__ float frcp(float x) {
    float r; asm("rcp.approx.f32 %0, %1;" : "=f"(r) : "f"(x)); return r;
}
__device__ __forceinline__ float fex2(float x) {
    float r; asm("ex2.approx.f32 %0, %1;" : "=f"(r) : "f"(x)); return r;
}
__device__ __forceinline__ float fsig(float x) {       // 1/(1+e^-x)
    return frcp(1.f + fex2(-1.4426950408889634f * x));
}
__device__ __forceinline__ float ftanh(float x) {      // 1 - 2/(1+e^{2x})
    return 1.f - 2.f * frcp(1.f + fex2(2.8853900817779268f * x));
}

#define BAR_ARRIVE(id, cnt) \
    asm volatile("bar.arrive %0, %1;" :: "r"(id), "r"(cnt) : "memory")
#define BAR_SYNCN(id, cnt) \
    asm volatile("bar.sync %0, %1;"   :: "r"(id), "r"(cnt) : "memory")

// ---------------- scratch (static device arrays; no cudaMalloc) --------
__device__ float g_hs[(size_t)SEQ * BATCH * HID];  // h history (streamed)
__device__ float g_hx[2][BATCH * HID];             // hot h exchange (L2)
__device__ unsigned g_flag[NBG * NUG * 32];        // per-CTA publish flags (128B apart)
__device__ unsigned g_cnt;                          // one-shot global barriers
__device__ volatile unsigned g_gen;

// =============================================================
// Warp-specialized LSTM scan + readout (R14 skeleton, best).
// R17: (1) fast MUFU gates; (2) 2-phase chunked h exchange:
// comm t<128 stage ranks 0-3 -> HRDA, t>=128 stage ranks 4-7 ->
// HRDB; compute overlaps lower-half h-GEMV with upper staging.
// Own-rank stagers skip the flag poll (CBAR gives visibility).
// =============================================================
#define WR    260   // W_hh row stride (floats)
#define WXR   68    // W_ih row stride
#define HS2   260   // H batch stride
#define HBUF2 (8 * HS2)      // 2080 floats per H parity buffer
#define LST2  132   // L batch stride
#define XB    68    // x batch stride
#define XQ    (8 * XB)       // 544 floats per x buffer (x4 quad)

#define SM_W   0
#define SM_WX  (128 * WR)            // 33280
#define SM_H   (SM_WX + 128 * WXR)   // 41984
#define SM_L   (SM_H + 2 * HBUF2)    // 46144
#define SM_X   (SM_L + 8 * LST2)     // 47200
#define SM_TOT (SM_X + 4 * XQ + 32)  // 49408 floats = 197632 B

#define BARID_GATE 1
#define BARID_HRDA 2
#define BARID_HRDB 3
#define BARID_CBAR 4

__device__ __forceinline__ void grid_barrier(int t) {
    if (t == 0) {
        unsigned cur = g_gen;
        __threadfence();
        if (atomicAdd(&g_cnt, 1u) == 127u) {
            atomicExch(&g_cnt, 0u);
            __threadfence();
            g_gen = cur + 1u;
        } else {
            while (g_gen == cur) { }
        }
        __threadfence();
    }
    __syncthreads();
}

__global__ void __launch_bounds__(512, 1)
k_lstm(const float* __restrict__ x, const float* __restrict__ h0,
       const float* __restrict__ c0, const float* __restrict__ Whh,
       const float* __restrict__ Wih, const float* __restrict__ bias,
       const float* __restrict__ Wout, const float* __restrict__ bout,
       float* __restrict__ out)
{
    extern __shared__ float smR[];
    float* Wsm  = smR + SM_W;    // W_hh [row r][k 0..255], stride WR
    float* Wxsm = smR + SM_WX;   // W_ih [row r][k 0..63], stride WXR
    float* Hsm  = smR + SM_H;    // h [par][b][k 0..255]
    float* Lsm  = smR + SM_L;    // lin [b][row 0..127]
    float* Xsm  = smR + SM_X;    // x [q 0..3][b][k 0..63]

    const int t     = threadIdx.x;
    const int bgrp  = blockIdx.x >> 3;      // 0..15
    const int urank = blockIdx.x & 7;       // 0..7
    const int b0g   = bgrp << 3;            // global batch base
    const int u0    = urank << 5;           // global unit base

    // ---- reset my publish flag ----
    unsigned* myflag = &g_flag[(bgrp * NUG + urank) * 32];
    if (t == 0) *myflag = 0u;

    // ---- load W_hh slice (128 rows x 256 K, linear k) ----
    for (int idx = t; idx < 128 * 64; idx += 512) {
        int r = idx >> 6, c4 = idx & 63;
        int grow = ((r >> 5) << 8) + u0 + (r & 31);
        float4 v = ((const float4*)Whh)[(size_t)grow * 64 + c4];
        *(float4*)(Wsm + r * WR + (c4 << 2)) = v;
    }
    // ---- load W_ih slice (128 rows x 64 K) ----
    for (int idx = t; idx < 128 * 16; idx += 512) {
        int r = idx >> 4, c4 = idx & 15;
        int grow = ((r >> 5) << 8) + u0 + (r & 31);
        float4 v = ((const float4*)Wih)[(size_t)grow * 16 + c4];
        *(float4*)(Wxsm + r * WXR + (c4 << 2)) = v;
    }
    // ---- init Hsm[0] from h0 ----
    {
        int b = t >> 6, c4 = t & 63;
        float4 v = ((const float4*)h0)[(size_t)(b0g + b) * 64 + c4];
        *(float4*)(Hsm + b * HS2 + (c4 << 2)) = v;
    }
    // ---- init Xsm[0]=x(0), Xsm[1]=x(1); xr = x(2) (t in [128,256)) ----
    float4 xr = make_float4(0.f, 0.f, 0.f, 0.f);
    if (t >= 128 && t < 256) {
        int tt = t - 128;
        int b = tt >> 4, c4 = tt & 15;
        *(float4*)(Xsm + 0 * XQ + b * XB + (c4 << 2)) =
            ((const float4*)x)[(size_t)(b0g + b) * 16 + c4];
        *(float4*)(Xsm + 1 * XQ + b * XB + (c4 << 2)) =
            ((const float4*)x)[(size_t)(BATCH + b0g + b) * 16 + c4];
        xr = ((const float4*)x)[(size_t)(2 * BATCH + b0g + b) * 16 + c4];
    }

    // ---- comm-thread state (t < 256) ----
    const int b_c = t >> 5;
    const int u_c = t & 31;
    const int ugt = u0 + u_c;
    float creg = 0.f, bi = 0.f, bf = 0.f, bg = 0.f, bo = 0.f;
    if (t < 256) {
        creg = c0[(size_t)(b0g + b_c) * HID + ugt];
        bi = bias[0 * HID + ugt];
        bf = bias[1 * HID + ugt];
        bg = bias[2 * HID + ugt];
        bo = bias[3 * HID + ugt];
    }
    // ---- 2-phase staging assignment (comm threads) ----
    // group A: t<128 -> rank = t>>5 (0..3); group B: t in [128,256) -> 4 + (t-128)>>5
    const int grpB = (t >= 128);
    const int tl   = t & 127;               // 0..127 within group
    const int rnk  = (grpB << 2) + (tl >> 5);   // source rank 0..7
    const int sid  = tl & 31;               // 0..31 within rank
    const int sb   = sid >> 2;              // batch 0..7
    const int fo   = (sid & 3) << 1;        // first float4 (of 8) in slice
    const unsigned* fsrc = &g_flag[(bgrp * NUG + rnk) * 32];
    const int hxo = (b0g + sb) * HID + (rnk << 5) + (fo << 2);
    const int hdo = sb * HS2 + (rnk << 5) + (fo << 2);

    grid_barrier(t);   // flags zeroed everywhere before first publish

    if (t < 256) {
        // ======================= COMM + GATES =======================
        #pragma unroll 1
        for (int step = 0; step < SEQ; step++) {
            const int par = step & 1;
            BAR_SYNCN(BARID_GATE, 512);          // Lsm(step) ready

            const float* Lb = Lsm + b_c * LST2;
            float iv = Lb[u_c]      + bi;
            float fv = Lb[32 + u_c] + bf;
            float gv = Lb[64 + u_c] + bg;
            float ov = Lb[96 + u_c] + bo;
            float ig = fsig(iv);
            float fg = fsig(fv);
            float gg = ftanh(gv);
            float og = fsig(ov);
            float cc = fg * creg + ig * gg;
            creg = cc;
            float hh = og * ftanh(cc);
            g_hx[par][(b0g + b_c) * HID + ugt] = hh;

            // x stage 2 ahead (group B threads own x)
            if (grpB && step + 2 < SEQ) {
                int b = tl >> 4, c4 = tl & 15;
                *(float4*)(Xsm + ((step + 2) & 3) * XQ + b * XB + (c4 << 2)) = xr;
                if (step + 3 < SEQ)
                    xr = ((const float4*)x)[(size_t)((step + 3) * BATCH + b0g + b) * 16 + c4];
            }

            BAR_SYNCN(BARID_CBAR, 256);          // all publishes issued
            if (t == 0) {
                unsigned nv = (unsigned)(step + 1);
                asm volatile("st.release.gpu.u32 [%0], %1;"
                             :: "l"(myflag), "r"(nv) : "memory");
            }

            if (step + 1 < SEQ) {
                // poll my source rank (skip if own: CBAR gives visibility)
                if (rnk != urank) {
                    unsigned v;
                    do {
                        asm volatile("ld.acquire.gpu.u32 %0, [%1];"
                                     : "=r"(v) : "l"(fsrc) : "memory");
                    } while (v < (unsigned)(step + 1));
                }
                float4 hva = *(const float4*)&g_hx[par][hxo];
                float4 hvb = *(const float4*)&g_hx[par][hxo + 4];
                float* Hd = Hsm + ((step + 1) & 1) * HBUF2 + hdo;
                *(float4*)(Hd)     = hva;
                *(float4*)(Hd + 4) = hvb;
                if (!grpB) BAR_ARRIVE(BARID_HRDA, 384);  // ranks 0-3 staged
                else       BAR_ARRIVE(BARID_HRDB, 384);  // ranks 4-7 staged
            }
            // history store off the handoff path
            __stcs(&g_hs[((size_t)step * BATCH + b0g + b_c) * HID + ugt], hh);
        }
    } else {
        // ========================= COMPUTE ==========================
        const int ct = t - 256;
        const int r  = ct >> 1;        // gate row 0..127
        const int bp = ct & 1;         // batch half
        const int bb = bp << 2;        // batch base 0 or 4
        const float* Wrow  = Wsm  + r * WR;
        const float* Wxrow = Wxsm + r * WXR;

        #pragma unroll 1
        for (int step = 0; step < SEQ; step++) {
            // ---- x-GEMV first (overlaps comm's publish/poll/stage) ----
            ull a0 = 0, a1 = 0, a2 = 0, a3 = 0;
            {
                const float* Xq = Xsm + (step & 3) * XQ + bb * XB;
                #pragma unroll
                for (int k2 = 0; k2 < 16; k2++) {
                    ulonglong2 wv = *(const ulonglong2*)(Wxrow + (k2 << 2));
                    ulonglong2 hv;
                    hv = *(const ulonglong2*)(Xq + 0 * XB + (k2 << 2));
                    FMA2(a0, wv.x, hv.x); FMA2(a0, wv.y, hv.y);
                    hv = *(const ulonglong2*)(Xq + 1 * XB + (k2 << 2));
                    FMA2(a1, wv.x, hv.x); FMA2(a1, wv.y, hv.y);
                    hv = *(const ulonglong2*)(Xq + 2 * XB + (k2 << 2));
                    FMA2(a2, wv.x, hv.x); FMA2(a2, wv.y, hv.y);
                    hv = *(const ulonglong2*)(Xq + 3 * XB + (k2 << 2));
                    FMA2(a3, wv.x, hv.x); FMA2(a3, wv.y, hv.y);
                }
            }
            const float* Hb = Hsm + (step & 1) * HBUF2 + bb * HS2;

            // ---- phase A: k < 128 (ranks 0-3) ----
            if (step > 0) BAR_SYNCN(BARID_HRDA, 384);
            #pragma unroll 8
            for (int k2 = 0; k2 < 32; k2++) {
                ulonglong2 wv = *(const ulonglong2*)(Wrow + (k2 << 2));
                ulonglong2 hv;
                hv = *(const ulonglong2*)(Hb + 0 * HS2 + (k2 << 2));
                FMA2(a0, wv.x, hv.x); FMA2(a0, wv.y, hv.y);
                hv = *(const ulonglong2*)(Hb + 1 * HS2 + (k2 << 2));
                FMA2(a1, wv.x, hv.x); FMA2(a1, wv.y, hv.y);
                hv = *(const ulonglong2*)(Hb + 2 * HS2 + (k2 << 2));
                FMA2(a2, wv.x, hv.x); FMA2(a2, wv.y, hv.y);
                hv = *(const ulonglong2*)(Hb + 3 * HS2 + (k2 << 2));
                FMA2(a3, wv.x, hv.x); FMA2(a3, wv.y, hv.y);
            }
            // ---- phase B: k >= 128 (ranks 4-7) ----
            if (step > 0) BAR_SYNCN(BARID_HRDB, 384);
            #pragma unroll 8
            for (int k2 = 32; k2 < 64; k2++) {
                ulonglong2 wv = *(const ulonglong2*)(Wrow + (k2 << 2));
                ulonglong2 hv;
                hv = *(const ulonglong2*)(Hb + 0 * HS2 + (k2 << 2));
                FMA2(a0, wv.x, hv.x); FMA2(a0, wv.y, hv.y);
                hv = *(const ulonglong2*)(Hb + 1 * HS2 + (k2 << 2));
                FMA2(a1, wv.x, hv.x); FMA2(a1, wv.y, hv.y);
                hv = *(const ulonglong2*)(Hb + 2 * HS2 + (k2 << 2));
                FMA2(a2, wv.x, hv.x); FMA2(a2, wv.y, hv.y);
                hv = *(const ulonglong2*)(Hb + 3 * HS2 + (k2 << 2));
                FMA2(a3, wv.x, hv.x); FMA2(a3, wv.y, hv.y);
            }

            // ---- Lsm: 4 scalar stores ----
            Lsm[(bb + 0) * LST2 + r] = hsum2(a0);
            Lsm[(bb + 1) * LST2 + r] = hsum2(a1);
            Lsm[(bb + 2) * LST2 + r] = hsum2(a2);
            Lsm[(bb + 3) * LST2 + r] = hsum2(a3);
            BAR_ARRIVE(BARID_GATE, 512);
        }
    }

    // ================= readout: out = hs @ Wout^T + bout =================
    __threadfence();
    grid_barrier(t);

    ulonglong2* WoS = (ulonglong2*)smR;            // [kc][64][19]
    ulonglong2* HsS = (ulonglong2*)(smR + SM_H);   // [64][19]

    for (int idx = t; idx < 4096; idx += 512) {
        int kc = idx >> 10, rem = idx & 1023, rr = rem >> 4, c = rem & 15;
        WoS[(kc * 64 + rr) * 19 + c] =
            ((const ulonglong2*)Wout)[(size_t)rr * 64 + kc * 16 + c];
    }
    const int tx  = t & 15;
    const int tyr = t >> 4;   // 0..31
    float bo4[4];
    #pragma unroll
    for (int j = 0; j < 4; j++) bo4[j] = __ldg(&bout[tx + 16 * j]);
    __syncthreads();

    for (int tile = 0; tile < 32; tile++) {
        size_t m0 = ((size_t)blockIdx.x * 32 + tile) * 64;
        ull ac[2][4];
        #pragma unroll
        for (int i = 0; i < 2; i++)
            #pragma unroll
            for (int j = 0; j < 4; j++) ac[i][j] = 0ull;

        for (int kc = 0; kc < 4; kc++) {
            __syncthreads();
            for (int idx = t; idx < 1024; idx += 512) {
                int rr = idx >> 4, c = idx & 15;
                HsS[rr * 19 + c] =
                    ((const ulonglong2*)g_hs)[(m0 + rr) * 64 + kc * 16 + c];
            }
            __syncthreads();
            #pragma unroll
            for (int k4 = 0; k4 < 16; k4++) {
                ulonglong2 a0 = HsS[tyr * 19 + k4];
                ulonglong2 a1 = HsS[(tyr + 32) * 19 + k4];
                #pragma unroll
                for (int j = 0; j < 4; j++) {
                    ulonglong2 b2 = WoS[(kc * 64 + tx + 16 * j) * 19 + k4];
                    FMA2(ac[0][j], a0.x, b2.x); FMA2(ac[0][j], a0.y, b2.y);
                    FMA2(ac[1][j], a1.x, b2.x); FMA2(ac[1][j], a1.y, b2.y);
                }
            }
        }
        #pragma unroll
        for (int i = 0; i < 2; i++) {
            size_t m = m0 + tyr + 32 * i;
            #pragma unroll
            for (int j = 0; j < 4; j++)
                out[m * OUTD + tx + 16 * j] = hsum2(ac[i][j]) + bo4[j];
        }
    }
}

// =============================================================
extern "C" void kernel_launch(void* const* d_in, const int* in_sizes, int n_in,
                              void* d_out, int out_size)
{
    (void)in_sizes; (void)n_in; (void)out_size;
    const float* x    = (const float*)d_in[0];
    const float* h0   = (const float*)d_in[1];
    const float* c0   = (const float*)d_in[2];
    const float* Wih  = (const float*)d_in[3];
    const float* Whh  = (const float*)d_in[4];
    const float* b    = (const float*)d_in[5];
    const float* Wout = (const float*)d_in[6];
    const float* bout = (const float*)d_in[7];
    float* out = (float*)d_out;

    const int smB = SM_TOT * 4;   // 197632 B

    cudaFuncSetAttribute(k_lstm, cudaFuncAttributeMaxDynamicSharedMemorySize, smB);

    k_lstm<<<NBG * NUG, 512, smB>>>(x, h0, c0, Whh, Wih, b, Wout, bout, out);
}